// round 15
// baseline (speedup 1.0000x reference)
#include <cuda_runtime.h>
#include <cuda_bf16.h>
#include <math.h>
#include <stdint.h>

// ---------------------------------------------------------------------------
// Problem constants
// ---------------------------------------------------------------------------
#define BATCH 4
#define SEQ   2048
#define DIM   1024
#define ROWS  (BATCH * SEQ)     // 8192
#define K3    (3 * DIM)         // 3072
#define K3P   (3 * SEQ)         // 6144

// ---------------------------------------------------------------------------
// Device scratch (static, allocation-free)
// ---------------------------------------------------------------------------
__device__ __nv_bfloat16 g_ax[(size_t)ROWS * K3];          // split x   [8192,3072]
__device__ __nv_bfloat16 g_bw[3][(size_t)DIM * K3];        // split W^T [1024,3072] x3
__device__ float         g_v [(size_t)ROWS * DIM];         // V fp32
__device__ __nv_bfloat16 g_aq[(size_t)ROWS * K3];          // split Q (A form)
__device__ __nv_bfloat16 g_bk[(size_t)ROWS * K3];          // split K (B form)
__device__ float         g_s [(size_t)BATCH * SEQ * SEQ];  // scores
__device__ __nv_bfloat16 g_ap[(size_t)ROWS * K3P];         // split P   [8192,6144]
__device__ __nv_bfloat16 g_bv[(size_t)BATCH * DIM * K3P];  // split V^T [4,1024,6144]

// ---------------------------------------------------------------------------
// Helpers
// ---------------------------------------------------------------------------
__device__ __forceinline__ uint32_t smem_u32(const void* p) {
    uint32_t a;
    asm("{ .reg .u64 t; cvta.to.shared.u64 t, %1; cvt.u32.u64 %0, t; }" : "=r"(a) : "l"(p));
    return a;
}
__device__ __forceinline__ void cp16(uint32_t dst, const void* src) {
    asm volatile("cp.async.cg.shared.global [%0], [%1], 16;" :: "r"(dst), "l"(src));
}
__device__ __forceinline__ void ldm_x4(uint32_t& r0, uint32_t& r1, uint32_t& r2, uint32_t& r3,
                                       uint32_t addr) {
    asm volatile("ldmatrix.sync.aligned.m8n8.x4.shared.b16 {%0,%1,%2,%3}, [%4];"
                 : "=r"(r0), "=r"(r1), "=r"(r2), "=r"(r3) : "r"(addr));
}
__device__ __forceinline__ void mma16816(float* d, uint32_t a0, uint32_t a1, uint32_t a2,
                                         uint32_t a3, uint32_t b0, uint32_t b1) {
    asm volatile("mma.sync.aligned.m16n8k16.row.col.f32.bf16.bf16.f32 "
                 "{%0,%1,%2,%3}, {%4,%5,%6,%7}, {%8,%9}, {%0,%1,%2,%3};"
                 : "+f"(d[0]), "+f"(d[1]), "+f"(d[2]), "+f"(d[3])
                 : "r"(a0), "r"(a1), "r"(a2), "r"(a3), "r"(b0), "r"(b1));
}
__device__ __forceinline__ void split_pair(float v0, float v1,
                                           __nv_bfloat162& h, __nv_bfloat162& l) {
    __nv_bfloat16 h0 = __float2bfloat16_rn(v0);
    __nv_bfloat16 h1 = __float2bfloat16_rn(v1);
    __nv_bfloat16 l0 = __float2bfloat16_rn(v0 - __bfloat162float(h0));
    __nv_bfloat16 l1 = __float2bfloat16_rn(v1 - __bfloat162float(h1));
    h = __nv_bfloat162(h0, h1);
    l = __nv_bfloat162(l0, l1);
}

// ---------------------------------------------------------------------------
// GEMM: C[m,n] = alpha * sum_k A[m,k] * B[n,k]   (A,B bf16 K-major)
// CTA tile 128x128, BK=32, 3-stage cp.async, 8 warps (2M x 4N), warp 64x32.
// 2 CTAs/SM.  (R7 config — proven fastest.)
// EPI: 0 = fp32 C ; 1 = bf16 split-A [hi,lo,hi] ; 2 = bf16 split-B [hi,hi,lo]
//      (split modes write rows of length 3*Nld)
// ---------------------------------------------------------------------------
#define GBM 128
#define GBN 128
#define GBK 32
#define APITCH 80u
#define TILE_BYTES (128u * APITCH)          // 10240 per operand
#define STAGE_BYTES (2u * TILE_BYTES)       // 20480
#define NSTAGE 3
#define GEMM_SMEM (NSTAGE * STAGE_BYTES)    // 61440

__device__ __forceinline__ void g_load_stage(const __nv_bfloat16* A, const __nv_bfloat16* B,
                                             int Kp, int kt, int slot, uint32_t sb, int tid)
{
    const __nv_bfloat16* a0 = A + (size_t)kt * GBK;
    const __nv_bfloat16* b0 = B + (size_t)kt * GBK;
    uint32_t ab = sb + (uint32_t)slot * STAGE_BYTES;
    uint32_t bb = ab + TILE_BYTES;
#pragma unroll
    for (int i = 0; i < 2; i++) {          // A: 128 rows x 4 chunks = 512
        int idx = tid + i * 256;
        int r = idx >> 2, c = idx & 3;
        cp16(ab + (uint32_t)r * APITCH + (uint32_t)c * 16u, a0 + (size_t)r * Kp + c * 8);
    }
#pragma unroll
    for (int i = 0; i < 2; i++) {          // B: 128 rows x 4 chunks = 512
        int idx = tid + i * 256;
        int r = idx >> 2, c = idx & 3;
        cp16(bb + (uint32_t)r * APITCH + (uint32_t)c * 16u, b0 + (size_t)r * Kp + c * 8);
    }
    asm volatile("cp.async.commit_group;" ::: "memory");
}

template <int EPI>
__global__ __launch_bounds__(256, 2)
void gemm_mma(const __nv_bfloat16* __restrict__ A,
              const __nv_bfloat16* __restrict__ B,
              void* __restrict__ Cv,
              int Kp, int Nld, float alpha,
              long long sA, long long sB, long long sC)
{
    extern __shared__ char smem_raw[];
    uint32_t sb = smem_u32(smem_raw);

    const int tid  = threadIdx.x;
    const int wid  = tid >> 5;
    const int lane = tid & 31;
    const int m0   = (wid & 1) * 64;       // 2 warps over M
    const int n0   = (wid >> 1) * 32;      // 4 warps over N

    A += (long long)blockIdx.z * sA + (long long)blockIdx.y * GBM * Kp;
    B += (long long)blockIdx.z * sB + (long long)blockIdx.x * GBN * Kp;

    const uint32_t a_lane_off = (uint32_t)(m0 + (lane & 15)) * APITCH
                              + (uint32_t)((lane >> 4) * 8) * 2u;
    const uint32_t b_lane_off = (uint32_t)(n0 + (lane & 7) + ((lane >> 4) * 8)) * APITCH
                              + (uint32_t)(((lane >> 3) & 1) * 8) * 2u;

    float acc[4][4][4];
#pragma unroll
    for (int i = 0; i < 4; i++)
#pragma unroll
        for (int j = 0; j < 4; j++)
#pragma unroll
            for (int r = 0; r < 4; r++) acc[i][j][r] = 0.0f;

    const int KT = Kp / GBK;

    g_load_stage(A, B, Kp, 0, 0, sb, tid);
    g_load_stage(A, B, Kp, 1, 1, sb, tid);

    int slot = 0;
    for (int kt = 0; kt < KT; kt++) {
        asm volatile("cp.async.wait_group 1;" ::: "memory");
        __syncthreads();

        if (kt + 2 < KT)
            g_load_stage(A, B, Kp, kt + 2, (slot + 2) % NSTAGE, sb, tid);
        else
            asm volatile("cp.async.commit_group;" ::: "memory");

        uint32_t abase = sb + (uint32_t)slot * STAGE_BYTES;
        uint32_t bbase = abase + TILE_BYTES;

#pragma unroll
        for (int ks = 0; ks < 2; ks++) {       // two k16 steps per BK=32
            uint32_t koff = (uint32_t)(ks * 16) * 2u;
            uint32_t af[4][4];
#pragma unroll
            for (int i = 0; i < 4; i++)
                ldm_x4(af[i][0], af[i][1], af[i][2], af[i][3],
                       abase + a_lane_off + (uint32_t)(i * 16) * APITCH + koff);
            uint32_t bf[2][4];
#pragma unroll
            for (int j = 0; j < 2; j++)
                ldm_x4(bf[j][0], bf[j][1], bf[j][2], bf[j][3],
                       bbase + b_lane_off + (uint32_t)(j * 16) * APITCH + koff);
#pragma unroll
            for (int i = 0; i < 4; i++) {
#pragma unroll
                for (int j = 0; j < 2; j++) {
                    mma16816(acc[i][2 * j + 0], af[i][0], af[i][1], af[i][2], af[i][3],
                             bf[j][0], bf[j][1]);
                    mma16816(acc[i][2 * j + 1], af[i][0], af[i][1], af[i][2], af[i][3],
                             bf[j][2], bf[j][3]);
                }
            }
        }
        slot = (slot + 1) % NSTAGE;
        __syncthreads();
    }

    // ---- epilogue ----
    const int erow = lane >> 2;
    const int ecol = (lane & 3) * 2;

    if (EPI == 0) {
        float* C = (float*)Cv + (long long)blockIdx.z * sC
                 + (long long)blockIdx.y * GBM * Nld + (long long)blockIdx.x * GBN;
#pragma unroll
        for (int i = 0; i < 4; i++) {
#pragma unroll
            for (int j = 0; j < 4; j++) {
                int row = m0 + i * 16 + erow;
                int col = n0 + j * 8 + ecol;
                float2 v0, v1;
                v0.x = alpha * acc[i][j][0];
                v0.y = alpha * acc[i][j][1];
                v1.x = alpha * acc[i][j][2];
                v1.y = alpha * acc[i][j][3];
                *reinterpret_cast<float2*>(C + (size_t)row * Nld + col) = v0;
                *reinterpret_cast<float2*>(C + (size_t)(row + 8) * Nld + col) = v1;
            }
        }
    } else {
        const size_t rs = (size_t)3 * Nld;   // split row stride
        __nv_bfloat16* O = (__nv_bfloat16*)Cv + (long long)blockIdx.z * sC
                         + (size_t)blockIdx.y * GBM * rs + (long long)blockIdx.x * GBN;
#pragma unroll
        for (int i = 0; i < 4; i++) {
#pragma unroll
            for (int j = 0; j < 4; j++) {
                int row = m0 + i * 16 + erow;
                int col = n0 + j * 8 + ecol;
#pragma unroll
                for (int h = 0; h < 2; h++) {
                    float v0 = alpha * acc[i][j][2 * h + 0];
                    float v1 = alpha * acc[i][j][2 * h + 1];
                    __nv_bfloat162 hi, lo;
                    split_pair(v0, v1, hi, lo);
                    __nv_bfloat16* base = O + (size_t)(row + 8 * h) * rs + col;
                    *reinterpret_cast<__nv_bfloat162*>(base) = hi;
                    if (EPI == 1) {   // A form: [hi, lo, hi]
                        *reinterpret_cast<__nv_bfloat162*>(base + Nld)     = lo;
                        *reinterpret_cast<__nv_bfloat162*>(base + 2 * Nld) = hi;
                    } else {          // B form: [hi, hi, lo]
                        *reinterpret_cast<__nv_bfloat162*>(base + Nld)     = hi;
                        *reinterpret_cast<__nv_bfloat162*>(base + 2 * Nld) = lo;
                    }
                }
            }
        }
    }
}

// ---------------------------------------------------------------------------
// split x (fp32 input) -> A operand [hi, lo, hi]
// ---------------------------------------------------------------------------
__device__ __forceinline__ void store8bf(__nv_bfloat16* p, const __nv_bfloat16* v) {
    uint4 u;
    u.x = ((uint32_t)__bfloat16_as_ushort(v[1]) << 16) | __bfloat16_as_ushort(v[0]);
    u.y = ((uint32_t)__bfloat16_as_ushort(v[3]) << 16) | __bfloat16_as_ushort(v[2]);
    u.z = ((uint32_t)__bfloat16_as_ushort(v[5]) << 16) | __bfloat16_as_ushort(v[4]);
    u.w = ((uint32_t)__bfloat16_as_ushort(v[7]) << 16) | __bfloat16_as_ushort(v[6]);
    *reinterpret_cast<uint4*>(p) = u;
}

__global__ __launch_bounds__(256)
void split_kernel(const float* __restrict__ in, __nv_bfloat16* __restrict__ out,
                  int C, long long n8)
{
    long long idx = (long long)blockIdx.x * blockDim.x + threadIdx.x;
    if (idx >= n8) return;
    long long e = idx * 8;
    long long r = e / C;
    int c = (int)(e - r * C);
    const float4* src = reinterpret_cast<const float4*>(in + e);
    float4 v0 = src[0], v1 = src[1];
    float xs[8] = {v0.x, v0.y, v0.z, v0.w, v1.x, v1.y, v1.z, v1.w};
    __nv_bfloat16 hi[8], lo[8];
#pragma unroll
    for (int j = 0; j < 8; j++) {
        hi[j] = __float2bfloat16_rn(xs[j]);
        lo[j] = __float2bfloat16_rn(xs[j] - __bfloat162float(hi[j]));
    }
    __nv_bfloat16* o = out + r * (long long)(3 * C) + c;
    store8bf(o, hi);
    store8bf(o + C, lo);
    store8bf(o + 2 * C, hi);
}

// ---------------------------------------------------------------------------
// Transpose + split: in f32 [z][K][N] -> out bf16 [z][N][3K] = [hi, hi, lo]
// 32(k) x 32(n) tiles; each thread writes a bf16x2 pair along k (4B stores).
// ---------------------------------------------------------------------------
__global__ __launch_bounds__(256)
void tsplit_kernel(const float* __restrict__ in, __nv_bfloat16* __restrict__ out,
                   int K, int N)
{
    __shared__ float tile[32][33];
    const float* inz = in + (long long)blockIdx.z * K * N;
    __nv_bfloat16* outz = out + (long long)blockIdx.z * N * (long long)(3 * K);
    int k0 = blockIdx.y * 32, n0 = blockIdx.x * 32;
    int tx = threadIdx.x & 31, ty = threadIdx.x >> 5;
#pragma unroll
    for (int i = ty; i < 32; i += 8)
        tile[i][tx] = inz[(long long)(k0 + i) * N + n0 + tx];
    __syncthreads();

    // write phase: 256 threads = 16 kpairs x 16 n; loop n twice
    int kp = threadIdx.x & 15;             // k pair index (2 k's each)
    int nb = threadIdx.x >> 4;             // 0..15
#pragma unroll
    for (int rep = 0; rep < 2; rep++) {
        int n = n0 + nb + rep * 16;
        int k = k0 + kp * 2;
        float x0 = tile[kp * 2 + 0][nb + rep * 16];
        float x1 = tile[kp * 2 + 1][nb + rep * 16];
        __nv_bfloat162 hi, lo;
        split_pair(x0, x1, hi, lo);
        __nv_bfloat16* o = outz + (long long)n * (3 * K) + k;
        *reinterpret_cast<__nv_bfloat162*>(o)         = hi;
        *reinterpret_cast<__nv_bfloat162*>(o + K)     = hi;
        *reinterpret_cast<__nv_bfloat162*>(o + 2 * K) = lo;
    }
}

// ---------------------------------------------------------------------------
// Fused softmax + split-P: one row per CTA, register-resident (2048 = 256*8),
// writes split-A bf16 [hi, lo, hi] directly.
// ---------------------------------------------------------------------------
__global__ __launch_bounds__(256)
void softmax_split_kernel(const float* __restrict__ s, __nv_bfloat16* __restrict__ ap)
{
    __shared__ float red[8];
    const int tid  = threadIdx.x;
    const int lane = tid & 31;
    const int wid  = tid >> 5;
    const float* p = s + (size_t)blockIdx.x * SEQ;

    float x[8];
#pragma unroll
    for (int i = 0; i < 8; i++) x[i] = p[tid + 256 * i];

    float m = x[0];
#pragma unroll
    for (int i = 1; i < 8; i++) m = fmaxf(m, x[i]);
#pragma unroll
    for (int o = 16; o > 0; o >>= 1) m = fmaxf(m, __shfl_xor_sync(0xFFFFFFFFu, m, o));
    if (lane == 0) red[wid] = m;
    __syncthreads();
    m = red[0];
#pragma unroll
    for (int w = 1; w < 8; w++) m = fmaxf(m, red[w]);
    __syncthreads();

    float sum = 0.0f;
#pragma unroll
    for (int i = 0; i < 8; i++) {
        x[i] = expf(x[i] - m);
        sum += x[i];
    }
#pragma unroll
    for (int o = 16; o > 0; o >>= 1) sum += __shfl_xor_sync(0xFFFFFFFFu, sum, o);
    if (lane == 0) red[wid] = sum;
    __syncthreads();
    sum = red[0];
#pragma unroll
    for (int w = 1; w < 8; w++) sum += red[w];
    const float inv = 1.0f / sum;

    __nv_bfloat16* o = ap + (size_t)blockIdx.x * K3P;
#pragma unroll
    for (int i = 0; i < 8; i++) {
        float v = x[i] * inv;
        __nv_bfloat16 hi = __float2bfloat16_rn(v);
        __nv_bfloat16 lo = __float2bfloat16_rn(v - __bfloat162float(hi));
        int c = tid + 256 * i;
        o[c] = hi;
        o[c + SEQ] = lo;
        o[c + 2 * SEQ] = hi;
    }
}

// ---------------------------------------------------------------------------
// kernel_launch
// ---------------------------------------------------------------------------
extern "C" void kernel_launch(void* const* d_in, const int* in_sizes, int n_in,
                              void* d_out, int out_size)
{
    const float* x  = (const float*)d_in[0];
    const float* wq = (const float*)d_in[1];
    const float* wk = (const float*)d_in[2];
    const float* wv = (const float*)d_in[3];
    float* out = (float*)d_out;

    void *pax, *pbw, *pv, *paq, *pbk, *ps, *pap, *pbv;
    cudaGetSymbolAddress(&pax, g_ax);
    cudaGetSymbolAddress(&pbw, g_bw);
    cudaGetSymbolAddress(&pv, g_v);
    cudaGetSymbolAddress(&paq, g_aq);
    cudaGetSymbolAddress(&pbk, g_bk);
    cudaGetSymbolAddress(&ps, g_s);
    cudaGetSymbolAddress(&pap, g_ap);
    cudaGetSymbolAddress(&pbv, g_bv);

    __nv_bfloat16* ax = (__nv_bfloat16*)pax;
    __nv_bfloat16* bw = (__nv_bfloat16*)pbw;
    float* v = (float*)pv;
    __nv_bfloat16* aq = (__nv_bfloat16*)paq;
    __nv_bfloat16* bk = (__nv_bfloat16*)pbk;
    float* s = (float*)ps;
    __nv_bfloat16* ap = (__nv_bfloat16*)pap;
    __nv_bfloat16* bv = (__nv_bfloat16*)pbv;

    cudaFuncSetAttribute(gemm_mma<0>, cudaFuncAttributeMaxDynamicSharedMemorySize, GEMM_SMEM);
    cudaFuncSetAttribute(gemm_mma<1>, cudaFuncAttributeMaxDynamicSharedMemorySize, GEMM_SMEM);
    cudaFuncSetAttribute(gemm_mma<2>, cudaFuncAttributeMaxDynamicSharedMemorySize, GEMM_SMEM);

    // 1) split x -> A operand [8192, 3072]
    {
        long long n8 = (long long)ROWS * DIM / 8;
        split_kernel<<<(unsigned)((n8 + 255) / 256), 256>>>(x, ax, DIM, n8);
    }
    // 2) transpose+split weights -> B operands [1024, 3072]
    {
        dim3 g(DIM / 32, DIM / 32, 1);
        tsplit_kernel<<<g, 256>>>(wq, bw + 0 * (size_t)DIM * K3, DIM, DIM);
        tsplit_kernel<<<g, 256>>>(wk, bw + 1 * (size_t)DIM * K3, DIM, DIM);
        tsplit_kernel<<<g, 256>>>(wv, bw + 2 * (size_t)DIM * K3, DIM, DIM);
    }
    // 3) projections with fused split epilogues
    {
        dim3 g(DIM / GBN, ROWS / GBM, 1);   // (8, 64, 1)
        gemm_mma<1><<<g, 256, GEMM_SMEM>>>(ax, bw + 0 * (size_t)DIM * K3, aq,
                                           K3, DIM, 1.0f, 0, 0, 0);
        gemm_mma<2><<<g, 256, GEMM_SMEM>>>(ax, bw + 1 * (size_t)DIM * K3, bk,
                                           K3, DIM, 1.0f, 0, 0, 0);
        gemm_mma<0><<<g, 256, GEMM_SMEM>>>(ax, bw + 2 * (size_t)DIM * K3, v,
                                           K3, DIM, 1.0f, 0, 0, 0);
    }
    // 4) scores = Q K^T / 32 per batch
    {
        dim3 g(SEQ / GBN, SEQ / GBM, BATCH);   // (16, 16, 4)
        gemm_mma<0><<<g, 256, GEMM_SMEM>>>(aq, bk, s, K3, SEQ, 1.0f / 32.0f,
                                           (long long)SEQ * K3, (long long)SEQ * K3,
                                           (long long)SEQ * SEQ);
    }
    // 5) fused softmax + split-P
    softmax_split_kernel<<<ROWS, 256>>>(s, ap);

    // 6) transpose+split V -> [4,1024,6144]
    {
        dim3 g(DIM / 32, SEQ / 32, BATCH);
        tsplit_kernel<<<g, 256>>>(v, bv, SEQ, DIM);
    }
    // 7) out = P V per batch
    {
        dim3 g(DIM / GBN, SEQ / GBM, BATCH);   // (8, 16, 4)
        gemm_mma<0><<<g, 256, GEMM_SMEM>>>(ap, bv, out, K3P, DIM, 1.0f,
                                           (long long)SEQ * K3P, (long long)DIM * K3P,
                                           (long long)SEQ * DIM);
    }
}

// round 16
// speedup vs baseline: 1.0000x; 1.0000x over previous
#include <cuda_runtime.h>
#include <cuda_bf16.h>
#include <math.h>
#include <stdint.h>

// ---------------------------------------------------------------------------
// Problem constants
// ---------------------------------------------------------------------------
#define BATCH 4
#define SEQ   2048
#define DIM   1024
#define ROWS  (BATCH * SEQ)     // 8192
#define K3    (3 * DIM)         // 3072
#define K3P   (3 * SEQ)         // 6144

// ---------------------------------------------------------------------------
// Device scratch (static, allocation-free)
// ---------------------------------------------------------------------------
__device__ __nv_bfloat16 g_ax[(size_t)ROWS * K3];          // split x   [8192,3072]
__device__ __nv_bfloat16 g_bw[3][(size_t)DIM * K3];        // split W^T [1024,3072] x3
__device__ float         g_v [(size_t)ROWS * DIM];         // V fp32
__device__ __nv_bfloat16 g_aq[(size_t)ROWS * K3];          // split Q (A form)
__device__ __nv_bfloat16 g_bk[(size_t)ROWS * K3];          // split K (B form)
__device__ float         g_s [(size_t)BATCH * SEQ * SEQ];  // scores
__device__ __nv_bfloat16 g_ap[(size_t)ROWS * K3P];         // split P   [8192,6144]
__device__ __nv_bfloat16 g_bv[(size_t)BATCH * DIM * K3P];  // split V^T [4,1024,6144]

// ---------------------------------------------------------------------------
// Helpers
// ---------------------------------------------------------------------------
__device__ __forceinline__ uint32_t smem_u32(const void* p) {
    uint32_t a;
    asm("{ .reg .u64 t; cvta.to.shared.u64 t, %1; cvt.u32.u64 %0, t; }" : "=r"(a) : "l"(p));
    return a;
}
__device__ __forceinline__ void cp16(uint32_t dst, const void* src) {
    asm volatile("cp.async.cg.shared.global [%0], [%1], 16;" :: "r"(dst), "l"(src));
}
__device__ __forceinline__ void ldm_x4(uint32_t& r0, uint32_t& r1, uint32_t& r2, uint32_t& r3,
                                       uint32_t addr) {
    asm volatile("ldmatrix.sync.aligned.m8n8.x4.shared.b16 {%0,%1,%2,%3}, [%4];"
                 : "=r"(r0), "=r"(r1), "=r"(r2), "=r"(r3) : "r"(addr));
}
__device__ __forceinline__ void mma16816(float* d, uint32_t a0, uint32_t a1, uint32_t a2,
                                         uint32_t a3, uint32_t b0, uint32_t b1) {
    asm volatile("mma.sync.aligned.m16n8k16.row.col.f32.bf16.bf16.f32 "
                 "{%0,%1,%2,%3}, {%4,%5,%6,%7}, {%8,%9}, {%0,%1,%2,%3};"
                 : "+f"(d[0]), "+f"(d[1]), "+f"(d[2]), "+f"(d[3])
                 : "r"(a0), "r"(a1), "r"(a2), "r"(a3), "r"(b0), "r"(b1));
}
__device__ __forceinline__ void split_pair(float v0, float v1,
                                           __nv_bfloat162& h, __nv_bfloat162& l) {
    __nv_bfloat16 h0 = __float2bfloat16_rn(v0);
    __nv_bfloat16 h1 = __float2bfloat16_rn(v1);
    __nv_bfloat16 l0 = __float2bfloat16_rn(v0 - __bfloat162float(h0));
    __nv_bfloat16 l1 = __float2bfloat16_rn(v1 - __bfloat162float(h1));
    h = __nv_bfloat162(h0, h1);
    l = __nv_bfloat162(l0, l1);
}

// ---------------------------------------------------------------------------
// GEMM: C[m,n] = alpha * sum_k A[m,k] * B[n,k]   (A,B bf16 K-major)
// CTA tile 128x128, BK=32, 3-stage cp.async, 8 warps (2M x 4N), warp 64x32.
// 2 CTAs/SM.  (R7 config — proven fastest.)
// EPI: 0 = fp32 C ; 1 = bf16 split-A [hi,lo,hi] ; 2 = bf16 split-B [hi,hi,lo]
//      (split modes write rows of length 3*Nld)
// ---------------------------------------------------------------------------
#define GBM 128
#define GBN 128
#define GBK 32
#define APITCH 80u
#define TILE_BYTES (128u * APITCH)          // 10240 per operand
#define STAGE_BYTES (2u * TILE_BYTES)       // 20480
#define NSTAGE 3
#define GEMM_SMEM (NSTAGE * STAGE_BYTES)    // 61440

__device__ __forceinline__ void g_load_stage(const __nv_bfloat16* A, const __nv_bfloat16* B,
                                             int Kp, int kt, int slot, uint32_t sb, int tid)
{
    const __nv_bfloat16* a0 = A + (size_t)kt * GBK;
    const __nv_bfloat16* b0 = B + (size_t)kt * GBK;
    uint32_t ab = sb + (uint32_t)slot * STAGE_BYTES;
    uint32_t bb = ab + TILE_BYTES;
#pragma unroll
    for (int i = 0; i < 2; i++) {          // A: 128 rows x 4 chunks = 512
        int idx = tid + i * 256;
        int r = idx >> 2, c = idx & 3;
        cp16(ab + (uint32_t)r * APITCH + (uint32_t)c * 16u, a0 + (size_t)r * Kp + c * 8);
    }
#pragma unroll
    for (int i = 0; i < 2; i++) {          // B: 128 rows x 4 chunks = 512
        int idx = tid + i * 256;
        int r = idx >> 2, c = idx & 3;
        cp16(bb + (uint32_t)r * APITCH + (uint32_t)c * 16u, b0 + (size_t)r * Kp + c * 8);
    }
    asm volatile("cp.async.commit_group;" ::: "memory");
}

template <int EPI>
__global__ __launch_bounds__(256, 2)
void gemm_mma(const __nv_bfloat16* __restrict__ A,
              const __nv_bfloat16* __restrict__ B,
              void* __restrict__ Cv,
              int Kp, int Nld, float alpha,
              long long sA, long long sB, long long sC)
{
    extern __shared__ char smem_raw[];
    uint32_t sb = smem_u32(smem_raw);

    const int tid  = threadIdx.x;
    const int wid  = tid >> 5;
    const int lane = tid & 31;
    const int m0   = (wid & 1) * 64;       // 2 warps over M
    const int n0   = (wid >> 1) * 32;      // 4 warps over N

    A += (long long)blockIdx.z * sA + (long long)blockIdx.y * GBM * Kp;
    B += (long long)blockIdx.z * sB + (long long)blockIdx.x * GBN * Kp;

    const uint32_t a_lane_off = (uint32_t)(m0 + (lane & 15)) * APITCH
                              + (uint32_t)((lane >> 4) * 8) * 2u;
    const uint32_t b_lane_off = (uint32_t)(n0 + (lane & 7) + ((lane >> 4) * 8)) * APITCH
                              + (uint32_t)(((lane >> 3) & 1) * 8) * 2u;

    float acc[4][4][4];
#pragma unroll
    for (int i = 0; i < 4; i++)
#pragma unroll
        for (int j = 0; j < 4; j++)
#pragma unroll
            for (int r = 0; r < 4; r++) acc[i][j][r] = 0.0f;

    const int KT = Kp / GBK;

    g_load_stage(A, B, Kp, 0, 0, sb, tid);
    g_load_stage(A, B, Kp, 1, 1, sb, tid);

    int slot = 0;
    for (int kt = 0; kt < KT; kt++) {
        asm volatile("cp.async.wait_group 1;" ::: "memory");
        __syncthreads();

        if (kt + 2 < KT)
            g_load_stage(A, B, Kp, kt + 2, (slot + 2) % NSTAGE, sb, tid);
        else
            asm volatile("cp.async.commit_group;" ::: "memory");

        uint32_t abase = sb + (uint32_t)slot * STAGE_BYTES;
        uint32_t bbase = abase + TILE_BYTES;

#pragma unroll
        for (int ks = 0; ks < 2; ks++) {       // two k16 steps per BK=32
            uint32_t koff = (uint32_t)(ks * 16) * 2u;
            uint32_t af[4][4];
#pragma unroll
            for (int i = 0; i < 4; i++)
                ldm_x4(af[i][0], af[i][1], af[i][2], af[i][3],
                       abase + a_lane_off + (uint32_t)(i * 16) * APITCH + koff);
            uint32_t bf[2][4];
#pragma unroll
            for (int j = 0; j < 2; j++)
                ldm_x4(bf[j][0], bf[j][1], bf[j][2], bf[j][3],
                       bbase + b_lane_off + (uint32_t)(j * 16) * APITCH + koff);
#pragma unroll
            for (int i = 0; i < 4; i++) {
#pragma unroll
                for (int j = 0; j < 2; j++) {
                    mma16816(acc[i][2 * j + 0], af[i][0], af[i][1], af[i][2], af[i][3],
                             bf[j][0], bf[j][1]);
                    mma16816(acc[i][2 * j + 1], af[i][0], af[i][1], af[i][2], af[i][3],
                             bf[j][2], bf[j][3]);
                }
            }
        }
        slot = (slot + 1) % NSTAGE;
        __syncthreads();
    }

    // ---- epilogue ----
    const int erow = lane >> 2;
    const int ecol = (lane & 3) * 2;

    if (EPI == 0) {
        float* C = (float*)Cv + (long long)blockIdx.z * sC
                 + (long long)blockIdx.y * GBM * Nld + (long long)blockIdx.x * GBN;
#pragma unroll
        for (int i = 0; i < 4; i++) {
#pragma unroll
            for (int j = 0; j < 4; j++) {
                int row = m0 + i * 16 + erow;
                int col = n0 + j * 8 + ecol;
                float2 v0, v1;
                v0.x = alpha * acc[i][j][0];
                v0.y = alpha * acc[i][j][1];
                v1.x = alpha * acc[i][j][2];
                v1.y = alpha * acc[i][j][3];
                *reinterpret_cast<float2*>(C + (size_t)row * Nld + col) = v0;
                *reinterpret_cast<float2*>(C + (size_t)(row + 8) * Nld + col) = v1;
            }
        }
    } else {
        const size_t rs = (size_t)3 * Nld;   // split row stride
        __nv_bfloat16* O = (__nv_bfloat16*)Cv + (long long)blockIdx.z * sC
                         + (size_t)blockIdx.y * GBM * rs + (long long)blockIdx.x * GBN;
#pragma unroll
        for (int i = 0; i < 4; i++) {
#pragma unroll
            for (int j = 0; j < 4; j++) {
                int row = m0 + i * 16 + erow;
                int col = n0 + j * 8 + ecol;
#pragma unroll
                for (int h = 0; h < 2; h++) {
                    float v0 = alpha * acc[i][j][2 * h + 0];
                    float v1 = alpha * acc[i][j][2 * h + 1];
                    __nv_bfloat162 hi, lo;
                    split_pair(v0, v1, hi, lo);
                    __nv_bfloat16* base = O + (size_t)(row + 8 * h) * rs + col;
                    *reinterpret_cast<__nv_bfloat162*>(base) = hi;
                    if (EPI == 1) {   // A form: [hi, lo, hi]
                        *reinterpret_cast<__nv_bfloat162*>(base + Nld)     = lo;
                        *reinterpret_cast<__nv_bfloat162*>(base + 2 * Nld) = hi;
                    } else {          // B form: [hi, hi, lo]
                        *reinterpret_cast<__nv_bfloat162*>(base + Nld)     = hi;
                        *reinterpret_cast<__nv_bfloat162*>(base + 2 * Nld) = lo;
                    }
                }
            }
        }
    }
}

// ---------------------------------------------------------------------------
// split x (fp32 input) -> A operand [hi, lo, hi]
// ---------------------------------------------------------------------------
__device__ __forceinline__ void store8bf(__nv_bfloat16* p, const __nv_bfloat16* v) {
    uint4 u;
    u.x = ((uint32_t)__bfloat16_as_ushort(v[1]) << 16) | __bfloat16_as_ushort(v[0]);
    u.y = ((uint32_t)__bfloat16_as_ushort(v[3]) << 16) | __bfloat16_as_ushort(v[2]);
    u.z = ((uint32_t)__bfloat16_as_ushort(v[5]) << 16) | __bfloat16_as_ushort(v[4]);
    u.w = ((uint32_t)__bfloat16_as_ushort(v[7]) << 16) | __bfloat16_as_ushort(v[6]);
    *reinterpret_cast<uint4*>(p) = u;
}

__global__ __launch_bounds__(256)
void split_kernel(const float* __restrict__ in, __nv_bfloat16* __restrict__ out,
                  int C, long long n8)
{
    long long idx = (long long)blockIdx.x * blockDim.x + threadIdx.x;
    if (idx >= n8) return;
    long long e = idx * 8;
    long long r = e / C;
    int c = (int)(e - r * C);
    const float4* src = reinterpret_cast<const float4*>(in + e);
    float4 v0 = src[0], v1 = src[1];
    float xs[8] = {v0.x, v0.y, v0.z, v0.w, v1.x, v1.y, v1.z, v1.w};
    __nv_bfloat16 hi[8], lo[8];
#pragma unroll
    for (int j = 0; j < 8; j++) {
        hi[j] = __float2bfloat16_rn(xs[j]);
        lo[j] = __float2bfloat16_rn(xs[j] - __bfloat162float(hi[j]));
    }
    __nv_bfloat16* o = out + r * (long long)(3 * C) + c;
    store8bf(o, hi);
    store8bf(o + C, lo);
    store8bf(o + 2 * C, hi);
}

// ---------------------------------------------------------------------------
// Transpose + split: in f32 [z][K][N] -> out bf16 [z][N][3K] = [hi, hi, lo]
// 32(k) x 32(n) tiles; each thread writes a bf16x2 pair along k (4B stores).
// ---------------------------------------------------------------------------
__global__ __launch_bounds__(256)
void tsplit_kernel(const float* __restrict__ in, __nv_bfloat16* __restrict__ out,
                   int K, int N)
{
    __shared__ float tile[32][33];
    const float* inz = in + (long long)blockIdx.z * K * N;
    __nv_bfloat16* outz = out + (long long)blockIdx.z * N * (long long)(3 * K);
    int k0 = blockIdx.y * 32, n0 = blockIdx.x * 32;
    int tx = threadIdx.x & 31, ty = threadIdx.x >> 5;
#pragma unroll
    for (int i = ty; i < 32; i += 8)
        tile[i][tx] = inz[(long long)(k0 + i) * N + n0 + tx];
    __syncthreads();

    // write phase: 256 threads = 16 kpairs x 16 n; loop n twice
    int kp = threadIdx.x & 15;             // k pair index (2 k's each)
    int nb = threadIdx.x >> 4;             // 0..15
#pragma unroll
    for (int rep = 0; rep < 2; rep++) {
        int n = n0 + nb + rep * 16;
        int k = k0 + kp * 2;
        float x0 = tile[kp * 2 + 0][nb + rep * 16];
        float x1 = tile[kp * 2 + 1][nb + rep * 16];
        __nv_bfloat162 hi, lo;
        split_pair(x0, x1, hi, lo);
        __nv_bfloat16* o = outz + (long long)n * (3 * K) + k;
        *reinterpret_cast<__nv_bfloat162*>(o)         = hi;
        *reinterpret_cast<__nv_bfloat162*>(o + K)     = hi;
        *reinterpret_cast<__nv_bfloat162*>(o + 2 * K) = lo;
    }
}

// ---------------------------------------------------------------------------
// Fused softmax + split-P: one row per CTA, register-resident (2048 = 256*8),
// writes split-A bf16 [hi, lo, hi] directly.
// ---------------------------------------------------------------------------
__global__ __launch_bounds__(256)
void softmax_split_kernel(const float* __restrict__ s, __nv_bfloat16* __restrict__ ap)
{
    __shared__ float red[8];
    const int tid  = threadIdx.x;
    const int lane = tid & 31;
    const int wid  = tid >> 5;
    const float* p = s + (size_t)blockIdx.x * SEQ;

    float x[8];
#pragma unroll
    for (int i = 0; i < 8; i++) x[i] = p[tid + 256 * i];

    float m = x[0];
#pragma unroll
    for (int i = 1; i < 8; i++) m = fmaxf(m, x[i]);
#pragma unroll
    for (int o = 16; o > 0; o >>= 1) m = fmaxf(m, __shfl_xor_sync(0xFFFFFFFFu, m, o));
    if (lane == 0) red[wid] = m;
    __syncthreads();
    m = red[0];
#pragma unroll
    for (int w = 1; w < 8; w++) m = fmaxf(m, red[w]);
    __syncthreads();

    float sum = 0.0f;
#pragma unroll
    for (int i = 0; i < 8; i++) {
        x[i] = expf(x[i] - m);
        sum += x[i];
    }
#pragma unroll
    for (int o = 16; o > 0; o >>= 1) sum += __shfl_xor_sync(0xFFFFFFFFu, sum, o);
    if (lane == 0) red[wid] = sum;
    __syncthreads();
    sum = red[0];
#pragma unroll
    for (int w = 1; w < 8; w++) sum += red[w];
    const float inv = 1.0f / sum;

    __nv_bfloat16* o = ap + (size_t)blockIdx.x * K3P;
#pragma unroll
    for (int i = 0; i < 8; i++) {
        float v = x[i] * inv;
        __nv_bfloat16 hi = __float2bfloat16_rn(v);
        __nv_bfloat16 lo = __float2bfloat16_rn(v - __bfloat162float(hi));
        int c = tid + 256 * i;
        o[c] = hi;
        o[c + SEQ] = lo;
        o[c + 2 * SEQ] = hi;
    }
}

// ---------------------------------------------------------------------------
// kernel_launch
// ---------------------------------------------------------------------------
extern "C" void kernel_launch(void* const* d_in, const int* in_sizes, int n_in,
                              void* d_out, int out_size)
{
    const float* x  = (const float*)d_in[0];
    const float* wq = (const float*)d_in[1];
    const float* wk = (const float*)d_in[2];
    const float* wv = (const float*)d_in[3];
    float* out = (float*)d_out;

    void *pax, *pbw, *pv, *paq, *pbk, *ps, *pap, *pbv;
    cudaGetSymbolAddress(&pax, g_ax);
    cudaGetSymbolAddress(&pbw, g_bw);
    cudaGetSymbolAddress(&pv, g_v);
    cudaGetSymbolAddress(&paq, g_aq);
    cudaGetSymbolAddress(&pbk, g_bk);
    cudaGetSymbolAddress(&ps, g_s);
    cudaGetSymbolAddress(&pap, g_ap);
    cudaGetSymbolAddress(&pbv, g_bv);

    __nv_bfloat16* ax = (__nv_bfloat16*)pax;
    __nv_bfloat16* bw = (__nv_bfloat16*)pbw;
    float* v = (float*)pv;
    __nv_bfloat16* aq = (__nv_bfloat16*)paq;
    __nv_bfloat16* bk = (__nv_bfloat16*)pbk;
    float* s = (float*)ps;
    __nv_bfloat16* ap = (__nv_bfloat16*)pap;
    __nv_bfloat16* bv = (__nv_bfloat16*)pbv;

    cudaFuncSetAttribute(gemm_mma<0>, cudaFuncAttributeMaxDynamicSharedMemorySize, GEMM_SMEM);
    cudaFuncSetAttribute(gemm_mma<1>, cudaFuncAttributeMaxDynamicSharedMemorySize, GEMM_SMEM);
    cudaFuncSetAttribute(gemm_mma<2>, cudaFuncAttributeMaxDynamicSharedMemorySize, GEMM_SMEM);

    // 1) split x -> A operand [8192, 3072]
    {
        long long n8 = (long long)ROWS * DIM / 8;
        split_kernel<<<(unsigned)((n8 + 255) / 256), 256>>>(x, ax, DIM, n8);
    }
    // 2) transpose+split weights -> B operands [1024, 3072]
    {
        dim3 g(DIM / 32, DIM / 32, 1);
        tsplit_kernel<<<g, 256>>>(wq, bw + 0 * (size_t)DIM * K3, DIM, DIM);
        tsplit_kernel<<<g, 256>>>(wk, bw + 1 * (size_t)DIM * K3, DIM, DIM);
        tsplit_kernel<<<g, 256>>>(wv, bw + 2 * (size_t)DIM * K3, DIM, DIM);
    }
    // 3) projections with fused split epilogues
    {
        dim3 g(DIM / GBN, ROWS / GBM, 1);   // (8, 64, 1)
        gemm_mma<1><<<g, 256, GEMM_SMEM>>>(ax, bw + 0 * (size_t)DIM * K3, aq,
                                           K3, DIM, 1.0f, 0, 0, 0);
        gemm_mma<2><<<g, 256, GEMM_SMEM>>>(ax, bw + 1 * (size_t)DIM * K3, bk,
                                           K3, DIM, 1.0f, 0, 0, 0);
        gemm_mma<0><<<g, 256, GEMM_SMEM>>>(ax, bw + 2 * (size_t)DIM * K3, v,
                                           K3, DIM, 1.0f, 0, 0, 0);
    }
    // 4) scores = Q K^T / 32 per batch
    {
        dim3 g(SEQ / GBN, SEQ / GBM, BATCH);   // (16, 16, 4)
        gemm_mma<0><<<g, 256, GEMM_SMEM>>>(aq, bk, s, K3, SEQ, 1.0f / 32.0f,
                                           (long long)SEQ * K3, (long long)SEQ * K3,
                                           (long long)SEQ * SEQ);
    }
    // 5) fused softmax + split-P
    softmax_split_kernel<<<ROWS, 256>>>(s, ap);

    // 6) transpose+split V -> [4,1024,6144]
    {
        dim3 g(DIM / 32, SEQ / 32, BATCH);
        tsplit_kernel<<<g, 256>>>(v, bv, SEQ, DIM);
    }
    // 7) out = P V per batch
    {
        dim3 g(DIM / GBN, SEQ / GBM, BATCH);   // (8, 16, 4)
        gemm_mma<0><<<g, 256, GEMM_SMEM>>>(ap, bv, out, K3P, DIM, 1.0f,
                                           (long long)SEQ * K3P, (long long)DIM * K3P,
                                           (long long)SEQ * DIM);
    }
}

// round 17
// speedup vs baseline: 1.0010x; 1.0009x over previous
#include <cuda_runtime.h>
#include <cuda_bf16.h>
#include <math.h>
#include <stdint.h>

// ---------------------------------------------------------------------------
// Problem constants
// ---------------------------------------------------------------------------
#define BATCH 4
#define SEQ   2048
#define DIM   1024
#define ROWS  (BATCH * SEQ)     // 8192
#define K3    (3 * DIM)         // 3072
#define K3P   (3 * SEQ)         // 6144

// ---------------------------------------------------------------------------
// Device scratch (static, allocation-free)
// ---------------------------------------------------------------------------
__device__ __nv_bfloat16 g_ax[(size_t)ROWS * K3];          // split x   [8192,3072]
__device__ __nv_bfloat16 g_bw[3][(size_t)DIM * K3];        // split W^T [1024,3072] x3
__device__ float         g_v [(size_t)ROWS * DIM];         // V fp32
__device__ __nv_bfloat16 g_aq[(size_t)ROWS * K3];          // split Q (A form)
__device__ __nv_bfloat16 g_bk[(size_t)ROWS * K3];          // split K (B form)
__device__ float         g_s [(size_t)BATCH * SEQ * SEQ];  // scores
__device__ __nv_bfloat16 g_ap[(size_t)ROWS * K3P];         // split P   [8192,6144]
__device__ __nv_bfloat16 g_bv[(size_t)BATCH * DIM * K3P];  // split V^T [4,1024,6144]

// ---------------------------------------------------------------------------
// Helpers
// ---------------------------------------------------------------------------
__device__ __forceinline__ uint32_t smem_u32(const void* p) {
    uint32_t a;
    asm("{ .reg .u64 t; cvta.to.shared.u64 t, %1; cvt.u32.u64 %0, t; }" : "=r"(a) : "l"(p));
    return a;
}
__device__ __forceinline__ void cp16(uint32_t dst, const void* src) {
    asm volatile("cp.async.cg.shared.global [%0], [%1], 16;" :: "r"(dst), "l"(src));
}
__device__ __forceinline__ void ldm_x4(uint32_t& r0, uint32_t& r1, uint32_t& r2, uint32_t& r3,
                                       uint32_t addr) {
    asm volatile("ldmatrix.sync.aligned.m8n8.x4.shared.b16 {%0,%1,%2,%3}, [%4];"
                 : "=r"(r0), "=r"(r1), "=r"(r2), "=r"(r3) : "r"(addr));
}
__device__ __forceinline__ void mma16816(float* d, uint32_t a0, uint32_t a1, uint32_t a2,
                                         uint32_t a3, uint32_t b0, uint32_t b1) {
    asm volatile("mma.sync.aligned.m16n8k16.row.col.f32.bf16.bf16.f32 "
                 "{%0,%1,%2,%3}, {%4,%5,%6,%7}, {%8,%9}, {%0,%1,%2,%3};"
                 : "+f"(d[0]), "+f"(d[1]), "+f"(d[2]), "+f"(d[3])
                 : "r"(a0), "r"(a1), "r"(a2), "r"(a3), "r"(b0), "r"(b1));
}
__device__ __forceinline__ void split_pair(float v0, float v1,
                                           __nv_bfloat162& h, __nv_bfloat162& l) {
    __nv_bfloat16 h0 = __float2bfloat16_rn(v0);
    __nv_bfloat16 h1 = __float2bfloat16_rn(v1);
    __nv_bfloat16 l0 = __float2bfloat16_rn(v0 - __bfloat162float(h0));
    __nv_bfloat16 l1 = __float2bfloat16_rn(v1 - __bfloat162float(h1));
    h = __nv_bfloat162(h0, h1);
    l = __nv_bfloat162(l0, l1);
}

// ---------------------------------------------------------------------------
// GEMM: C[m,n] = alpha * sum_k A[m,k] * B[n,k]   (A,B bf16 K-major)
// CTA tile 128x128, BK=32, 3-stage cp.async, 8 warps (2M x 4N), warp 64x32.
// 2 CTAs/SM.  (R7 config — proven fastest.)
// EPI: 0 = fp32 C ; 1 = bf16 split-A [hi,lo,hi] ; 2 = bf16 split-B [hi,hi,lo]
//      (split modes write rows of length 3*Nld)
// ---------------------------------------------------------------------------
#define GBM 128
#define GBN 128
#define GBK 32
#define APITCH 80u
#define TILE_BYTES (128u * APITCH)          // 10240 per operand
#define STAGE_BYTES (2u * TILE_BYTES)       // 20480
#define NSTAGE 3
#define GEMM_SMEM (NSTAGE * STAGE_BYTES)    // 61440

__device__ __forceinline__ void g_load_stage(const __nv_bfloat16* A, const __nv_bfloat16* B,
                                             int Kp, int kt, int slot, uint32_t sb, int tid)
{
    const __nv_bfloat16* a0 = A + (size_t)kt * GBK;
    const __nv_bfloat16* b0 = B + (size_t)kt * GBK;
    uint32_t ab = sb + (uint32_t)slot * STAGE_BYTES;
    uint32_t bb = ab + TILE_BYTES;
#pragma unroll
    for (int i = 0; i < 2; i++) {          // A: 128 rows x 4 chunks = 512
        int idx = tid + i * 256;
        int r = idx >> 2, c = idx & 3;
        cp16(ab + (uint32_t)r * APITCH + (uint32_t)c * 16u, a0 + (size_t)r * Kp + c * 8);
    }
#pragma unroll
    for (int i = 0; i < 2; i++) {          // B: 128 rows x 4 chunks = 512
        int idx = tid + i * 256;
        int r = idx >> 2, c = idx & 3;
        cp16(bb + (uint32_t)r * APITCH + (uint32_t)c * 16u, b0 + (size_t)r * Kp + c * 8);
    }
    asm volatile("cp.async.commit_group;" ::: "memory");
}

template <int EPI>
__global__ __launch_bounds__(256, 2)
void gemm_mma(const __nv_bfloat16* __restrict__ A,
              const __nv_bfloat16* __restrict__ B,
              void* __restrict__ Cv,
              int Kp, int Nld, float alpha,
              long long sA, long long sB, long long sC)
{
    extern __shared__ char smem_raw[];
    uint32_t sb = smem_u32(smem_raw);

    const int tid  = threadIdx.x;
    const int wid  = tid >> 5;
    const int lane = tid & 31;
    const int m0   = (wid & 1) * 64;       // 2 warps over M
    const int n0   = (wid >> 1) * 32;      // 4 warps over N

    A += (long long)blockIdx.z * sA + (long long)blockIdx.y * GBM * Kp;
    B += (long long)blockIdx.z * sB + (long long)blockIdx.x * GBN * Kp;

    const uint32_t a_lane_off = (uint32_t)(m0 + (lane & 15)) * APITCH
                              + (uint32_t)((lane >> 4) * 8) * 2u;
    const uint32_t b_lane_off = (uint32_t)(n0 + (lane & 7) + ((lane >> 4) * 8)) * APITCH
                              + (uint32_t)(((lane >> 3) & 1) * 8) * 2u;

    float acc[4][4][4];
#pragma unroll
    for (int i = 0; i < 4; i++)
#pragma unroll
        for (int j = 0; j < 4; j++)
#pragma unroll
            for (int r = 0; r < 4; r++) acc[i][j][r] = 0.0f;

    const int KT = Kp / GBK;

    g_load_stage(A, B, Kp, 0, 0, sb, tid);
    g_load_stage(A, B, Kp, 1, 1, sb, tid);

    int slot = 0;
    for (int kt = 0; kt < KT; kt++) {
        asm volatile("cp.async.wait_group 1;" ::: "memory");
        __syncthreads();

        if (kt + 2 < KT)
            g_load_stage(A, B, Kp, kt + 2, (slot + 2) % NSTAGE, sb, tid);
        else
            asm volatile("cp.async.commit_group;" ::: "memory");

        uint32_t abase = sb + (uint32_t)slot * STAGE_BYTES;
        uint32_t bbase = abase + TILE_BYTES;

#pragma unroll
        for (int ks = 0; ks < 2; ks++) {       // two k16 steps per BK=32
            uint32_t koff = (uint32_t)(ks * 16) * 2u;
            uint32_t af[4][4];
#pragma unroll
            for (int i = 0; i < 4; i++)
                ldm_x4(af[i][0], af[i][1], af[i][2], af[i][3],
                       abase + a_lane_off + (uint32_t)(i * 16) * APITCH + koff);
            uint32_t bf[2][4];
#pragma unroll
            for (int j = 0; j < 2; j++)
                ldm_x4(bf[j][0], bf[j][1], bf[j][2], bf[j][3],
                       bbase + b_lane_off + (uint32_t)(j * 16) * APITCH + koff);
#pragma unroll
            for (int i = 0; i < 4; i++) {
#pragma unroll
                for (int j = 0; j < 2; j++) {
                    mma16816(acc[i][2 * j + 0], af[i][0], af[i][1], af[i][2], af[i][3],
                             bf[j][0], bf[j][1]);
                    mma16816(acc[i][2 * j + 1], af[i][0], af[i][1], af[i][2], af[i][3],
                             bf[j][2], bf[j][3]);
                }
            }
        }
        slot = (slot + 1) % NSTAGE;
        __syncthreads();
    }

    // ---- epilogue ----
    const int erow = lane >> 2;
    const int ecol = (lane & 3) * 2;

    if (EPI == 0) {
        float* C = (float*)Cv + (long long)blockIdx.z * sC
                 + (long long)blockIdx.y * GBM * Nld + (long long)blockIdx.x * GBN;
#pragma unroll
        for (int i = 0; i < 4; i++) {
#pragma unroll
            for (int j = 0; j < 4; j++) {
                int row = m0 + i * 16 + erow;
                int col = n0 + j * 8 + ecol;
                float2 v0, v1;
                v0.x = alpha * acc[i][j][0];
                v0.y = alpha * acc[i][j][1];
                v1.x = alpha * acc[i][j][2];
                v1.y = alpha * acc[i][j][3];
                *reinterpret_cast<float2*>(C + (size_t)row * Nld + col) = v0;
                *reinterpret_cast<float2*>(C + (size_t)(row + 8) * Nld + col) = v1;
            }
        }
    } else {
        const size_t rs = (size_t)3 * Nld;   // split row stride
        __nv_bfloat16* O = (__nv_bfloat16*)Cv + (long long)blockIdx.z * sC
                         + (size_t)blockIdx.y * GBM * rs + (long long)blockIdx.x * GBN;
#pragma unroll
        for (int i = 0; i < 4; i++) {
#pragma unroll
            for (int j = 0; j < 4; j++) {
                int row = m0 + i * 16 + erow;
                int col = n0 + j * 8 + ecol;
#pragma unroll
                for (int h = 0; h < 2; h++) {
                    float v0 = alpha * acc[i][j][2 * h + 0];
                    float v1 = alpha * acc[i][j][2 * h + 1];
                    __nv_bfloat162 hi, lo;
                    split_pair(v0, v1, hi, lo);
                    __nv_bfloat16* base = O + (size_t)(row + 8 * h) * rs + col;
                    *reinterpret_cast<__nv_bfloat162*>(base) = hi;
                    if (EPI == 1) {   // A form: [hi, lo, hi]
                        *reinterpret_cast<__nv_bfloat162*>(base + Nld)     = lo;
                        *reinterpret_cast<__nv_bfloat162*>(base + 2 * Nld) = hi;
                    } else {          // B form: [hi, hi, lo]
                        *reinterpret_cast<__nv_bfloat162*>(base + Nld)     = hi;
                        *reinterpret_cast<__nv_bfloat162*>(base + 2 * Nld) = lo;
                    }
                }
            }
        }
    }
}

// ---------------------------------------------------------------------------
// split x (fp32 input) -> A operand [hi, lo, hi]
// ---------------------------------------------------------------------------
__device__ __forceinline__ void store8bf(__nv_bfloat16* p, const __nv_bfloat16* v) {
    uint4 u;
    u.x = ((uint32_t)__bfloat16_as_ushort(v[1]) << 16) | __bfloat16_as_ushort(v[0]);
    u.y = ((uint32_t)__bfloat16_as_ushort(v[3]) << 16) | __bfloat16_as_ushort(v[2]);
    u.z = ((uint32_t)__bfloat16_as_ushort(v[5]) << 16) | __bfloat16_as_ushort(v[4]);
    u.w = ((uint32_t)__bfloat16_as_ushort(v[7]) << 16) | __bfloat16_as_ushort(v[6]);
    *reinterpret_cast<uint4*>(p) = u;
}

__global__ __launch_bounds__(256)
void split_kernel(const float* __restrict__ in, __nv_bfloat16* __restrict__ out,
                  int C, long long n8)
{
    long long idx = (long long)blockIdx.x * blockDim.x + threadIdx.x;
    if (idx >= n8) return;
    long long e = idx * 8;
    long long r = e / C;
    int c = (int)(e - r * C);
    const float4* src = reinterpret_cast<const float4*>(in + e);
    float4 v0 = src[0], v1 = src[1];
    float xs[8] = {v0.x, v0.y, v0.z, v0.w, v1.x, v1.y, v1.z, v1.w};
    __nv_bfloat16 hi[8], lo[8];
#pragma unroll
    for (int j = 0; j < 8; j++) {
        hi[j] = __float2bfloat16_rn(xs[j]);
        lo[j] = __float2bfloat16_rn(xs[j] - __bfloat162float(hi[j]));
    }
    __nv_bfloat16* o = out + r * (long long)(3 * C) + c;
    store8bf(o, hi);
    store8bf(o + C, lo);
    store8bf(o + 2 * C, hi);
}

// ---------------------------------------------------------------------------
// Transpose + split: in f32 [z][K][N] -> out bf16 [z][N][3K] = [hi, hi, lo]
// 32(k) x 32(n) tiles; each thread writes a bf16x2 pair along k (4B stores).
// ---------------------------------------------------------------------------
__global__ __launch_bounds__(256)
void tsplit_kernel(const float* __restrict__ in, __nv_bfloat16* __restrict__ out,
                   int K, int N)
{
    __shared__ float tile[32][33];
    const float* inz = in + (long long)blockIdx.z * K * N;
    __nv_bfloat16* outz = out + (long long)blockIdx.z * N * (long long)(3 * K);
    int k0 = blockIdx.y * 32, n0 = blockIdx.x * 32;
    int tx = threadIdx.x & 31, ty = threadIdx.x >> 5;
#pragma unroll
    for (int i = ty; i < 32; i += 8)
        tile[i][tx] = inz[(long long)(k0 + i) * N + n0 + tx];
    __syncthreads();

    // write phase: 256 threads = 16 kpairs x 16 n; loop n twice
    int kp = threadIdx.x & 15;             // k pair index (2 k's each)
    int nb = threadIdx.x >> 4;             // 0..15
#pragma unroll
    for (int rep = 0; rep < 2; rep++) {
        int n = n0 + nb + rep * 16;
        int k = k0 + kp * 2;
        float x0 = tile[kp * 2 + 0][nb + rep * 16];
        float x1 = tile[kp * 2 + 1][nb + rep * 16];
        __nv_bfloat162 hi, lo;
        split_pair(x0, x1, hi, lo);
        __nv_bfloat16* o = outz + (long long)n * (3 * K) + k;
        *reinterpret_cast<__nv_bfloat162*>(o)         = hi;
        *reinterpret_cast<__nv_bfloat162*>(o + K)     = hi;
        *reinterpret_cast<__nv_bfloat162*>(o + 2 * K) = lo;
    }
}

// ---------------------------------------------------------------------------
// Fused softmax + split-P: one row per CTA, register-resident (2048 = 256*8),
// writes split-A bf16 [hi, lo, hi] directly.
// ---------------------------------------------------------------------------
__global__ __launch_bounds__(256)
void softmax_split_kernel(const float* __restrict__ s, __nv_bfloat16* __restrict__ ap)
{
    __shared__ float red[8];
    const int tid  = threadIdx.x;
    const int lane = tid & 31;
    const int wid  = tid >> 5;
    const float* p = s + (size_t)blockIdx.x * SEQ;

    float x[8];
#pragma unroll
    for (int i = 0; i < 8; i++) x[i] = p[tid + 256 * i];

    float m = x[0];
#pragma unroll
    for (int i = 1; i < 8; i++) m = fmaxf(m, x[i]);
#pragma unroll
    for (int o = 16; o > 0; o >>= 1) m = fmaxf(m, __shfl_xor_sync(0xFFFFFFFFu, m, o));
    if (lane == 0) red[wid] = m;
    __syncthreads();
    m = red[0];
#pragma unroll
    for (int w = 1; w < 8; w++) m = fmaxf(m, red[w]);
    __syncthreads();

    float sum = 0.0f;
#pragma unroll
    for (int i = 0; i < 8; i++) {
        x[i] = expf(x[i] - m);
        sum += x[i];
    }
#pragma unroll
    for (int o = 16; o > 0; o >>= 1) sum += __shfl_xor_sync(0xFFFFFFFFu, sum, o);
    if (lane == 0) red[wid] = sum;
    __syncthreads();
    sum = red[0];
#pragma unroll
    for (int w = 1; w < 8; w++) sum += red[w];
    const float inv = 1.0f / sum;

    __nv_bfloat16* o = ap + (size_t)blockIdx.x * K3P;
#pragma unroll
    for (int i = 0; i < 8; i++) {
        float v = x[i] * inv;
        __nv_bfloat16 hi = __float2bfloat16_rn(v);
        __nv_bfloat16 lo = __float2bfloat16_rn(v - __bfloat162float(hi));
        int c = tid + 256 * i;
        o[c] = hi;
        o[c + SEQ] = lo;
        o[c + 2 * SEQ] = hi;
    }
}

// ---------------------------------------------------------------------------
// kernel_launch
// ---------------------------------------------------------------------------
extern "C" void kernel_launch(void* const* d_in, const int* in_sizes, int n_in,
                              void* d_out, int out_size)
{
    const float* x  = (const float*)d_in[0];
    const float* wq = (const float*)d_in[1];
    const float* wk = (const float*)d_in[2];
    const float* wv = (const float*)d_in[3];
    float* out = (float*)d_out;

    void *pax, *pbw, *pv, *paq, *pbk, *ps, *pap, *pbv;
    cudaGetSymbolAddress(&pax, g_ax);
    cudaGetSymbolAddress(&pbw, g_bw);
    cudaGetSymbolAddress(&pv, g_v);
    cudaGetSymbolAddress(&paq, g_aq);
    cudaGetSymbolAddress(&pbk, g_bk);
    cudaGetSymbolAddress(&ps, g_s);
    cudaGetSymbolAddress(&pap, g_ap);
    cudaGetSymbolAddress(&pbv, g_bv);

    __nv_bfloat16* ax = (__nv_bfloat16*)pax;
    __nv_bfloat16* bw = (__nv_bfloat16*)pbw;
    float* v = (float*)pv;
    __nv_bfloat16* aq = (__nv_bfloat16*)paq;
    __nv_bfloat16* bk = (__nv_bfloat16*)pbk;
    float* s = (float*)ps;
    __nv_bfloat16* ap = (__nv_bfloat16*)pap;
    __nv_bfloat16* bv = (__nv_bfloat16*)pbv;

    cudaFuncSetAttribute(gemm_mma<0>, cudaFuncAttributeMaxDynamicSharedMemorySize, GEMM_SMEM);
    cudaFuncSetAttribute(gemm_mma<1>, cudaFuncAttributeMaxDynamicSharedMemorySize, GEMM_SMEM);
    cudaFuncSetAttribute(gemm_mma<2>, cudaFuncAttributeMaxDynamicSharedMemorySize, GEMM_SMEM);

    // 1) split x -> A operand [8192, 3072]
    {
        long long n8 = (long long)ROWS * DIM / 8;
        split_kernel<<<(unsigned)((n8 + 255) / 256), 256>>>(x, ax, DIM, n8);
    }
    // 2) transpose+split weights -> B operands [1024, 3072]
    {
        dim3 g(DIM / 32, DIM / 32, 1);
        tsplit_kernel<<<g, 256>>>(wq, bw + 0 * (size_t)DIM * K3, DIM, DIM);
        tsplit_kernel<<<g, 256>>>(wk, bw + 1 * (size_t)DIM * K3, DIM, DIM);
        tsplit_kernel<<<g, 256>>>(wv, bw + 2 * (size_t)DIM * K3, DIM, DIM);
    }
    // 3) projections with fused split epilogues
    {
        dim3 g(DIM / GBN, ROWS / GBM, 1);   // (8, 64, 1)
        gemm_mma<1><<<g, 256, GEMM_SMEM>>>(ax, bw + 0 * (size_t)DIM * K3, aq,
                                           K3, DIM, 1.0f, 0, 0, 0);
        gemm_mma<2><<<g, 256, GEMM_SMEM>>>(ax, bw + 1 * (size_t)DIM * K3, bk,
                                           K3, DIM, 1.0f, 0, 0, 0);
        gemm_mma<0><<<g, 256, GEMM_SMEM>>>(ax, bw + 2 * (size_t)DIM * K3, v,
                                           K3, DIM, 1.0f, 0, 0, 0);
    }
    // 4) scores = Q K^T / 32 per batch
    {
        dim3 g(SEQ / GBN, SEQ / GBM, BATCH);   // (16, 16, 4)
        gemm_mma<0><<<g, 256, GEMM_SMEM>>>(aq, bk, s, K3, SEQ, 1.0f / 32.0f,
                                           (long long)SEQ * K3, (long long)SEQ * K3,
                                           (long long)SEQ * SEQ);
    }
    // 5) fused softmax + split-P
    softmax_split_kernel<<<ROWS, 256>>>(s, ap);

    // 6) transpose+split V -> [4,1024,6144]
    {
        dim3 g(DIM / 32, SEQ / 32, BATCH);
        tsplit_kernel<<<g, 256>>>(v, bv, SEQ, DIM);
    }
    // 7) out = P V per batch
    {
        dim3 g(DIM / GBN, SEQ / GBM, BATCH);   // (8, 16, 4)
        gemm_mma<0><<<g, 256, GEMM_SMEM>>>(ap, bv, out, K3P, DIM, 1.0f,
                                           (long long)SEQ * K3P, (long long)DIM * K3P,
                                           (long long)SEQ * DIM);
    }
}